// round 1
// baseline (speedup 1.0000x reference)
#include <cuda_runtime.h>
#include <cstdint>

// Problem constants
#define BB 4
#define NN 8192
#define DIM 256
#define HH 8
#define HD 32
#define INTERNAL 256          // H*HD
#define QKVO_COLS 1024        // 4*INTERNAL
#define TOKENS (BB*NN)        // 32768
#define SCALE_F 0.17677669529663687f   // 32^-0.5
#define NSPLIT 16
#define CHUNK (NN / NSPLIT)   // 512

// -------- static scratch (no allocations allowed) --------
__device__ float g_qkvo[(size_t)TOKENS * QKVO_COLS];     // 134 MB
__device__ float g_resO[(size_t)TOKENS * INTERNAL];      // 33.5 MB
__device__ float g_kv_part[32 * NSPLIT * HD * HD];       // 2 MB
__device__ float g_ks_part[32 * NSPLIT * HD];
__device__ float g_vs_part[32 * NSPLIT * HD];
__device__ float g_kv[32 * HD * HD];
__device__ float g_kmean[32 * HD];
__device__ float g_vmean[32 * HD];

// =====================================================================
// Generic fp32 GEMM: C[M,N] = A[M,K] @ B[N,K]^T + bias[N]
// Block tile 128x64, BK=16, 256 threads, 8x4 per thread.
// =====================================================================
#define BM 128
#define BN 64
#define BK 16

__global__ __launch_bounds__(256) void gemm_bias_kernel(
    const float* __restrict__ A, const float* __restrict__ Bm,
    const float* __restrict__ bias, float* __restrict__ C,
    int M, int N, int K)
{
    __shared__ float As[BK][BM];
    __shared__ float Bs[BK][BN];

    const int tid = threadIdx.x;
    const int bm = blockIdx.y * BM;
    const int bn = blockIdx.x * BN;
    const int tx = tid & 15;   // n dir (x4)
    const int ty = tid >> 4;   // m dir (x8)

    float acc[8][4];
#pragma unroll
    for (int i = 0; i < 8; i++)
#pragma unroll
        for (int j = 0; j < 4; j++) acc[i][j] = 0.f;

    for (int k0 = 0; k0 < K; k0 += BK) {
        // Load A tile: 128x16 = 512 float4, 2 per thread
#pragma unroll
        for (int i = 0; i < 2; i++) {
            int f = tid * 2 + i;
            int row = f >> 2;
            int kq = (f & 3) * 4;
            float4 v = *(const float4*)&A[(size_t)(bm + row) * K + k0 + kq];
            As[kq + 0][row] = v.x;
            As[kq + 1][row] = v.y;
            As[kq + 2][row] = v.z;
            As[kq + 3][row] = v.w;
        }
        // Load B tile: 64x16 = 256 float4, 1 per thread
        {
            int f = tid;
            int row = f >> 2;
            int kq = (f & 3) * 4;
            float4 v = *(const float4*)&Bm[(size_t)(bn + row) * K + k0 + kq];
            Bs[kq + 0][row] = v.x;
            Bs[kq + 1][row] = v.y;
            Bs[kq + 2][row] = v.z;
            Bs[kq + 3][row] = v.w;
        }
        __syncthreads();

#pragma unroll
        for (int k = 0; k < BK; k++) {
            float4 a0 = *(const float4*)&As[k][ty * 8];
            float4 a1 = *(const float4*)&As[k][ty * 8 + 4];
            float4 bb = *(const float4*)&Bs[k][tx * 4];
            float a[8] = {a0.x, a0.y, a0.z, a0.w, a1.x, a1.y, a1.z, a1.w};
            float b[4] = {bb.x, bb.y, bb.z, bb.w};
#pragma unroll
            for (int i = 0; i < 8; i++)
#pragma unroll
                for (int j = 0; j < 4; j++)
                    acc[i][j] += a[i] * b[j];
        }
        __syncthreads();
    }

    float4 bv = *(const float4*)&bias[bn + tx * 4];
#pragma unroll
    for (int i = 0; i < 8; i++) {
        int m = bm + ty * 8 + i;
        float4 o;
        o.x = acc[i][0] + bv.x;
        o.y = acc[i][1] + bv.y;
        o.z = acc[i][2] + bv.z;
        o.w = acc[i][3] + bv.w;
        *(float4*)&C[(size_t)m * N + bn + tx * 4] = o;
    }
}

__device__ __forceinline__ float elu1(float x) {
    return x > 0.f ? x + 1.f : __expf(x);
}

// =====================================================================
// kv_state / ksum / vsum partials, split-K over n (deterministic, no atomics)
// grid: (32 bh-pairs, NSPLIT), block 1024
// =====================================================================
__global__ __launch_bounds__(1024) void kv_partial_kernel(
    const float* __restrict__ qkvo,
    const float* __restrict__ sin_, const float* __restrict__ cos_)
{
    const int p = blockIdx.x;         // b*8 + h
    const int s = blockIdx.y;
    const int b = p >> 3, h = p & 7;
    const int tid = threadIdx.x;
    const int d = tid >> 5, e = tid & 31;
    const int r = tid >> 6;           // staging row 0..7 (tid<512)
    const int c = tid & 63;           // staging col 0..63

    __shared__ float ks_s[8][32];
    __shared__ float vs_s[8][32];
    __shared__ float part[8][64];

    float acc = 0.f;
    float psum = 0.f;
    const int n0 = s * CHUNK;

    for (int g = 0; g < CHUNK; g += 8) {
        if (tid < 512) {
            int n = n0 + g + r;
            size_t row = (size_t)(b * NN + n) * QKVO_COLS;
            if (c < 32) {
                float kh = elu1(qkvo[row + INTERNAL + h * HD + c]);
                psum += kh;
                float partner = __shfl_xor_sync(0xffffffffu, kh, 1);
                float rot = (c & 1) ? partner : -partner;
                ks_s[r][c] = kh * cos_[n * HD + c] + rot * sin_[n * HD + c];
            } else {
                int ee = c - 32;
                float v = qkvo[row + 2 * INTERNAL + h * HD + ee];
                psum += v;
                vs_s[r][ee] = v;
            }
        }
        __syncthreads();
#pragma unroll
        for (int rr = 0; rr < 8; rr++)
            acc += ks_s[rr][d] * vs_s[rr][e];
        __syncthreads();
    }

    g_kv_part[((size_t)p * NSPLIT + s) * (HD * HD) + tid] = acc;

    if (tid < 512) part[r][c] = psum;
    __syncthreads();
    if (tid < 64) {
        float t = 0.f;
#pragma unroll
        for (int rr = 0; rr < 8; rr++) t += part[rr][tid];
        if (tid < 32) g_ks_part[(p * NSPLIT + s) * HD + tid] = t;
        else          g_vs_part[(p * NSPLIT + s) * HD + (tid - 32)] = t;
    }
}

// grid: 32 blocks x 1024 threads
__global__ __launch_bounds__(1024) void kv_reduce_kernel()
{
    const int p = blockIdx.x;
    const int tid = threadIdx.x;
    const float s2 = SCALE_F / (float)NN;
    float acc = 0.f;
#pragma unroll
    for (int s = 0; s < NSPLIT; s++)
        acc += g_kv_part[((size_t)p * NSPLIT + s) * (HD * HD) + tid];
    g_kv[p * (HD * HD) + tid] = acc * s2;
    if (tid < 32) {
        float a = 0.f, v = 0.f;
#pragma unroll
        for (int s = 0; s < NSPLIT; s++) {
            a += g_ks_part[(p * NSPLIT + s) * HD + tid];
            v += g_vs_part[(p * NSPLIT + s) * HD + tid];
        }
        g_kmean[p * HD + tid] = a / (float)NN;
        g_vmean[p * HD + tid] = v / (float)NN;
    }
}

// =====================================================================
// Fused elementwise: elu(q)+1, z, theta_shift, attn = qs@kv, lepe conv,
// res*(1+1/(z+eps)) - z*vmean, (+lepe)*o  ->  g_resO
// grid: TOKENS/32 blocks, 256 threads (thread = channel c, warp = head)
// =====================================================================
#define T3 32
__global__ __launch_bounds__(256) void combine_kernel(
    const float* __restrict__ qkvo,
    const float* __restrict__ sin_, const float* __restrict__ cos_,
    const float* __restrict__ W_lepe, const float* __restrict__ b_lepe,
    float* __restrict__ resO)
{
    const int tok0 = blockIdx.x * T3;
    const int b = tok0 >> 13;         // /8192
    const int c = threadIdx.x;
    const int h = c >> 5, d = c & 31;
    const int p = b * HH + h;

    __shared__ float kv_s[HH * HD * HD];   // 32KB
    __shared__ float km_s[INTERNAL];
    __shared__ float vm_s[INTERNAL];
    __shared__ float qs_s[HH][HD];

    for (int i = c; i < HH * HD * HD; i += 256)
        kv_s[i] = g_kv[(size_t)(b * HH) * (HD * HD) + i];
    km_s[c] = g_kmean[p * HD + d];
    vm_s[c] = g_vmean[p * HD + d];
    const float w0 = W_lepe[c * 3 + 0];
    const float w1 = W_lepe[c * 3 + 1];
    const float w2 = W_lepe[c * 3 + 2];
    const float bl = b_lepe[c];
    __syncthreads();

    for (int t = 0; t < T3; t++) {
        const int tok = tok0 + t;
        const int n = tok & (NN - 1);
        const size_t row = (size_t)tok * QKVO_COLS;

        float qh = elu1(qkvo[row + c]);

        // z = SCALE * dot(qh, kmean) over head dim (warp reduce)
        float zp = qh * km_s[c];
#pragma unroll
        for (int o = 16; o; o >>= 1) zp += __shfl_xor_sync(0xffffffffu, zp, o);
        float z = zp * SCALE_F;

        // theta shift
        float partner = __shfl_xor_sync(0xffffffffu, qh, 1);
        float rot = (d & 1) ? partner : -partner;
        float qs = qh * cos_[n * HD + d] + rot * sin_[n * HD + d];

        qs_s[h][d] = qs;
        __syncwarp();
        float attn = 0.f;
#pragma unroll
        for (int dd = 0; dd < HD; dd++)
            attn += qs_s[h][dd] * kv_s[h * (HD * HD) + dd * HD + d];
        __syncwarp();

        float v  = qkvo[row + 2 * INTERNAL + c];
        float vp = (n > 0)      ? qkvo[row - QKVO_COLS + 2 * INTERNAL + c] : 0.f;
        float vn = (n < NN - 1) ? qkvo[row + QKVO_COLS + 2 * INTERNAL + c] : 0.f;
        float lepe = vp * w0 + v * w1 + vn * w2 + bl;

        float res = attn * (1.f + 1.f / (z + 1e-6f)) - z * vm_s[c];
        float oo = qkvo[row + 3 * INTERNAL + c];
        resO[(size_t)tok * INTERNAL + c] = (res + lepe) * oo;
    }
}

// =====================================================================
extern "C" void kernel_launch(void* const* d_in, const int* in_sizes, int n_in,
                              void* d_out, int out_size)
{
    const float* x      = (const float*)d_in[0];
    const float* sin_   = (const float*)d_in[1];
    const float* cos_   = (const float*)d_in[2];
    const float* W_qkvo = (const float*)d_in[3];
    const float* b_qkvo = (const float*)d_in[4];
    const float* W_lepe = (const float*)d_in[5];
    const float* b_lepe = (const float*)d_in[6];
    const float* W_proj = (const float*)d_in[7];
    const float* b_proj = (const float*)d_in[8];
    float* out = (float*)d_out;

    float *qkvo_p, *resO_p;
    cudaGetSymbolAddress((void**)&qkvo_p, g_qkvo);
    cudaGetSymbolAddress((void**)&resO_p, g_resO);

    // 1) qkvo = x @ W_qkvo^T + b_qkvo   [32768 x 1024]
    gemm_bias_kernel<<<dim3(QKVO_COLS / BN, TOKENS / BM), 256>>>(
        x, W_qkvo, b_qkvo, qkvo_p, TOKENS, QKVO_COLS, DIM);

    // 2) kv_state / kmean / vmean partials + deterministic reduce
    kv_partial_kernel<<<dim3(32, NSPLIT), 1024>>>(qkvo_p, sin_, cos_);
    kv_reduce_kernel<<<32, 1024>>>();

    // 3) fused elementwise -> res*o
    combine_kernel<<<TOKENS / T3, 256>>>(qkvo_p, sin_, cos_, W_lepe, b_lepe, resO_p);

    // 4) out = resO @ W_proj^T + b_proj  [32768 x 256]
    gemm_bias_kernel<<<dim3(DIM / BN, TOKENS / BM), 256>>>(
        resO_p, W_proj, b_proj, out, TOKENS, DIM, INTERNAL);
}

// round 5
// speedup vs baseline: 1.4384x; 1.4384x over previous
#include <cuda_runtime.h>
#include <cstdint>

// Problem constants
#define BB 4
#define NN 8192
#define DIM 256
#define HH 8
#define HD 32
#define INTERNAL 256          // H*HD
#define QKVO_COLS 1024        // 4*INTERNAL
#define TOKENS (BB*NN)        // 32768
#define SCALE_F 0.17677669529663687f   // 32^-0.5
#define NSPLIT 16
#define CHUNK (NN / NSPLIT)   // 512

// -------- static scratch (no allocations allowed) --------
__device__ float g_qkvo[(size_t)TOKENS * QKVO_COLS];     // 134 MB
__device__ float g_resO[(size_t)TOKENS * INTERNAL];      // 33.5 MB
__device__ float g_kv_part[32 * NSPLIT * HD * HD];       // 2 MB
__device__ float g_ks_part[32 * NSPLIT * HD];
__device__ float g_vs_part[32 * NSPLIT * HD];
__device__ float g_kv[32 * HD * HD];
__device__ float g_kmean[32 * HD];
__device__ float g_vmean[32 * HD];

// =====================================================================
// PTX helpers (arch-agnostic: cp.async + mma.sync, sm_80+)
// =====================================================================
__device__ __forceinline__ uint32_t smem_u32(const void* p) {
    uint32_t a;
    asm("{ .reg .u64 t; cvta.to.shared.u64 t, %1; cvt.u32.u64 %0, t; }"
        : "=r"(a) : "l"(p));
    return a;
}
__device__ __forceinline__ void cp16(uint32_t dst, const void* src) {
    asm volatile("cp.async.cg.shared.global [%0], [%1], 16;" :: "r"(dst), "l"(src));
}
#define CP_COMMIT() asm volatile("cp.async.commit_group;" ::: "memory")
#define CP_WAIT1()  asm volatile("cp.async.wait_group 1;" ::: "memory")

__device__ __forceinline__ uint32_t f2tf32(float x) {
    uint32_t r;
    asm("cvt.rna.tf32.f32 %0, %1;" : "=r"(r) : "f"(x));
    return r;
}

#define MMA8(c, a, b) \
    asm volatile("mma.sync.aligned.m16n8k8.row.col.f32.tf32.tf32.f32 " \
        "{%0,%1,%2,%3}, {%4,%5,%6,%7}, {%8,%9}, {%0,%1,%2,%3};" \
        : "+f"((c)[0]), "+f"((c)[1]), "+f"((c)[2]), "+f"((c)[3]) \
        : "r"((a)[0]), "r"((a)[1]), "r"((a)[2]), "r"((a)[3]), \
          "r"((b)[0]), "r"((b)[1]))

// =====================================================================
// tf32 mma.sync GEMM: C[M,ldC] = A[M,K] @ B[N,K]^T + bias
// CTA tile 128x128, K-chunks of 32, cp.async double buffer.
// Fragment-order SMEM layout:
//   As[slab(4)][mt(8)][r(4)][lane(32)]  (16KB)
//   Bs[slab(4)][nt(16)][r(2)][lane(32)] (16KB)
// A element (m,k): slab=k>>3, r=((k&4)>>1)|((m&8)>>3), lane=(m&7)*4+(k&3)
// B element (n,k): slab=k>>3, r=(k&4)>>2,              lane=(n&7)*4+(k&3)
// Each GMEM float4 (fixed m, k..k+3) is one contiguous 16B SMEM chunk.
// =====================================================================
#define STAGE_BYTES 32768
#define GEMM_SMEM (2 * STAGE_BYTES)

__global__ __launch_bounds__(256, 2) void gemm_mma_kernel(
    const float* __restrict__ A, const float* __restrict__ Bm,
    const float* __restrict__ bias, float* __restrict__ C,
    int K, int ldC)
{
    extern __shared__ __align__(16) float smf[];
    const uint32_t sb = smem_u32(smf);
    const int tid = threadIdx.x;
    const int wid = tid >> 5, l = tid & 31;
    const int wm = wid >> 2, wn = wid & 3;     // warp grid 2(M) x 4(N)
    const int bm = blockIdx.y * 128;
    const int bn = blockIdx.x * 128;

    // Staging address precompute: idx = tid + 256*i covers 1024 float4
    // (rows 0..127, 8 float4 of k each)
    uint32_t a_dst[4], b_dst[4];
    const float *a_src[4], *b_src[4];
#pragma unroll
    for (int i = 0; i < 4; i++) {
        int idx = tid + 256 * i;
        int m = idx >> 3;
        int kq = (idx & 7) << 2;
        int slab = kq >> 3;
        int ra = ((kq & 4) >> 1) | ((m & 8) >> 3);
        a_dst[i] = (uint32_t)((((slab * 8 + (m >> 4)) * 4 + ra) * 32 + (m & 7) * 4) * 4);
        a_src[i] = A + (size_t)(bm + m) * K + kq;
        int rb = (kq & 4) >> 2;
        b_dst[i] = (uint32_t)(16384 + ((((slab * 16 + (m >> 3)) * 2 + rb) * 32 + (m & 7) * 4) * 4));
        b_src[i] = Bm + (size_t)(bn + m) * K + kq;
    }

    const int KCH = K / 32;

    // Prologue: stages 0,1
#pragma unroll
    for (int c = 0; c < 2; c++) {
        uint32_t base = sb + c * STAGE_BYTES;
#pragma unroll
        for (int i = 0; i < 4; i++) cp16(base + a_dst[i], a_src[i] + c * 32);
#pragma unroll
        for (int i = 0; i < 4; i++) cp16(base + b_dst[i], b_src[i] + c * 32);
        CP_COMMIT();
    }

    float acc[4][4][4] = {};

    for (int kc = 0; kc < KCH; kc++) {
        CP_WAIT1();
        __syncthreads();
        const float* As_ = smf + (kc & 1) * 8192;
        const float* Bs_ = As_ + 4096;

#pragma unroll
        for (int slab = 0; slab < 4; slab++) {
            uint32_t afr[4][4], bfr[4][2];
#pragma unroll
            for (int mt = 0; mt < 4; mt++)
#pragma unroll
                for (int r = 0; r < 4; r++)
                    afr[mt][r] = f2tf32(As_[((slab * 8 + wm * 4 + mt) * 4 + r) * 32 + l]);
#pragma unroll
            for (int nt = 0; nt < 4; nt++)
#pragma unroll
                for (int r = 0; r < 2; r++)
                    bfr[nt][r] = f2tf32(Bs_[((slab * 16 + wn * 4 + nt) * 2 + r) * 32 + l]);
#pragma unroll
            for (int mt = 0; mt < 4; mt++)
#pragma unroll
                for (int nt = 0; nt < 4; nt++)
                    MMA8(acc[mt][nt], afr[mt], bfr[nt]);
        }
        __syncthreads();

        if (kc + 2 < KCH) {
            uint32_t base = sb + (kc & 1) * STAGE_BYTES;
#pragma unroll
            for (int i = 0; i < 4; i++) cp16(base + a_dst[i], a_src[i] + (kc + 2) * 32);
#pragma unroll
            for (int i = 0; i < 4; i++) cp16(base + b_dst[i], b_src[i] + (kc + 2) * 32);
        }
        CP_COMMIT();   // keep group counting consistent even when empty
    }

    // Epilogue: c0:(row, col) c1:(row, col+1) c2:(row+8,col) c3:(row+8,col+1)
    const int row0 = bm + wm * 64 + (l >> 2);
    const int col0 = bn + wn * 32 + (l & 3) * 2;
#pragma unroll
    for (int mt = 0; mt < 4; mt++) {
        const int r0 = row0 + mt * 16;
#pragma unroll
        for (int nt = 0; nt < 4; nt++) {
            const int cc = col0 + nt * 8;
            const float bx = bias[cc], by = bias[cc + 1];
            float2 v0, v1;
            v0.x = acc[mt][nt][0] + bx;
            v0.y = acc[mt][nt][1] + by;
            v1.x = acc[mt][nt][2] + bx;
            v1.y = acc[mt][nt][3] + by;
            *(float2*)&C[(size_t)r0 * ldC + cc] = v0;
            *(float2*)&C[(size_t)(r0 + 8) * ldC + cc] = v1;
        }
    }
}

// =====================================================================
__device__ __forceinline__ float elu1(float x) {
    return x > 0.f ? x + 1.f : __expf(x);
}

// =====================================================================
// kv_state / ksum / vsum partials, split over n (deterministic, no atomics)
// =====================================================================
__global__ __launch_bounds__(1024) void kv_partial_kernel(
    const float* __restrict__ qkvo,
    const float* __restrict__ sin_, const float* __restrict__ cos_)
{
    const int p = blockIdx.x;         // b*8 + h
    const int s = blockIdx.y;
    const int b = p >> 3, h = p & 7;
    const int tid = threadIdx.x;
    const int d = tid >> 5, e = tid & 31;
    const int r = tid >> 6;           // staging row 0..7 (tid<512)
    const int c = tid & 63;           // staging col 0..63

    __shared__ float ks_s[8][32];
    __shared__ float vs_s[8][32];
    __shared__ float part[8][64];

    float acc = 0.f;
    float psum = 0.f;
    const int n0 = s * CHUNK;

    for (int g = 0; g < CHUNK; g += 8) {
        if (tid < 512) {
            int n = n0 + g + r;
            size_t row = (size_t)(b * NN + n) * QKVO_COLS;
            if (c < 32) {
                float kh = elu1(qkvo[row + INTERNAL + h * HD + c]);
                psum += kh;
                float partner = __shfl_xor_sync(0xffffffffu, kh, 1);
                float rot = (c & 1) ? partner : -partner;
                ks_s[r][c] = kh * cos_[n * HD + c] + rot * sin_[n * HD + c];
            } else {
                int ee = c - 32;
                float v = qkvo[row + 2 * INTERNAL + h * HD + ee];
                psum += v;
                vs_s[r][ee] = v;
            }
        }
        __syncthreads();
#pragma unroll
        for (int rr = 0; rr < 8; rr++)
            acc += ks_s[rr][d] * vs_s[rr][e];
        __syncthreads();
    }

    g_kv_part[((size_t)p * NSPLIT + s) * (HD * HD) + tid] = acc;

    if (tid < 512) part[r][c] = psum;
    __syncthreads();
    if (tid < 64) {
        float t = 0.f;
#pragma unroll
        for (int rr = 0; rr < 8; rr++) t += part[rr][tid];
        if (tid < 32) g_ks_part[(p * NSPLIT + s) * HD + tid] = t;
        else          g_vs_part[(p * NSPLIT + s) * HD + (tid - 32)] = t;
    }
}

__global__ __launch_bounds__(1024) void kv_reduce_kernel()
{
    const int p = blockIdx.x;
    const int tid = threadIdx.x;
    const float s2 = SCALE_F / (float)NN;
    float acc = 0.f;
#pragma unroll
    for (int s = 0; s < NSPLIT; s++)
        acc += g_kv_part[((size_t)p * NSPLIT + s) * (HD * HD) + tid];
    g_kv[p * (HD * HD) + tid] = acc * s2;
    if (tid < 32) {
        float a = 0.f, v = 0.f;
#pragma unroll
        for (int s = 0; s < NSPLIT; s++) {
            a += g_ks_part[(p * NSPLIT + s) * HD + tid];
            v += g_vs_part[(p * NSPLIT + s) * HD + tid];
        }
        g_kmean[p * HD + tid] = a / (float)NN;
        g_vmean[p * HD + tid] = v / (float)NN;
    }
}

// =====================================================================
// Fused elementwise combine
// =====================================================================
#define T3 32
__global__ __launch_bounds__(256) void combine_kernel(
    const float* __restrict__ qkvo,
    const float* __restrict__ sin_, const float* __restrict__ cos_,
    const float* __restrict__ W_lepe, const float* __restrict__ b_lepe,
    float* __restrict__ resO)
{
    const int tok0 = blockIdx.x * T3;
    const int b = tok0 >> 13;         // /8192
    const int c = threadIdx.x;
    const int h = c >> 5, d = c & 31;
    const int p = b * HH + h;

    __shared__ float kv_s[HH * HD * HD];   // 32KB
    __shared__ float km_s[INTERNAL];
    __shared__ float vm_s[INTERNAL];
    __shared__ float qs_s[HH][HD];

    for (int i = c; i < HH * HD * HD; i += 256)
        kv_s[i] = g_kv[(size_t)(b * HH) * (HD * HD) + i];
    km_s[c] = g_kmean[p * HD + d];
    vm_s[c] = g_vmean[p * HD + d];
    const float w0 = W_lepe[c * 3 + 0];
    const float w1 = W_lepe[c * 3 + 1];
    const float w2 = W_lepe[c * 3 + 2];
    const float bl = b_lepe[c];
    __syncthreads();

    for (int t = 0; t < T3; t++) {
        const int tok = tok0 + t;
        const int n = tok & (NN - 1);
        const size_t row = (size_t)tok * QKVO_COLS;

        float qh = elu1(qkvo[row + c]);

        float zp = qh * km_s[c];
#pragma unroll
        for (int o = 16; o; o >>= 1) zp += __shfl_xor_sync(0xffffffffu, zp, o);
        float z = zp * SCALE_F;

        float partner = __shfl_xor_sync(0xffffffffu, qh, 1);
        float rot = (d & 1) ? partner : -partner;
        float qs = qh * cos_[n * HD + d] + rot * sin_[n * HD + d];

        qs_s[h][d] = qs;
        __syncwarp();
        float attn = 0.f;
#pragma unroll
        for (int dd = 0; dd < HD; dd++)
            attn += qs_s[h][dd] * kv_s[h * (HD * HD) + dd * HD + d];
        __syncwarp();

        float v  = qkvo[row + 2 * INTERNAL + c];
        float vp = (n > 0)      ? qkvo[row - QKVO_COLS + 2 * INTERNAL + c] : 0.f;
        float vn = (n < NN - 1) ? qkvo[row + QKVO_COLS + 2 * INTERNAL + c] : 0.f;
        float lepe = vp * w0 + v * w1 + vn * w2 + bl;

        float res = attn * (1.f + 1.f / (z + 1e-6f)) - z * vm_s[c];
        float oo = qkvo[row + 3 * INTERNAL + c];
        resO[(size_t)tok * INTERNAL + c] = (res + lepe) * oo;
    }
}

// =====================================================================
extern "C" void kernel_launch(void* const* d_in, const int* in_sizes, int n_in,
                              void* d_out, int out_size)
{
    const float* x      = (const float*)d_in[0];
    const float* sin_   = (const float*)d_in[1];
    const float* cos_   = (const float*)d_in[2];
    const float* W_qkvo = (const float*)d_in[3];
    const float* b_qkvo = (const float*)d_in[4];
    const float* W_lepe = (const float*)d_in[5];
    const float* b_lepe = (const float*)d_in[6];
    const float* W_proj = (const float*)d_in[7];
    const float* b_proj = (const float*)d_in[8];
    float* out = (float*)d_out;

    float *qkvo_p, *resO_p;
    cudaGetSymbolAddress((void**)&qkvo_p, g_qkvo);
    cudaGetSymbolAddress((void**)&resO_p, g_resO);

    cudaFuncSetAttribute(gemm_mma_kernel,
                         cudaFuncAttributeMaxDynamicSharedMemorySize, GEMM_SMEM);

    // 1) qkvo = x @ W_qkvo^T + b_qkvo   [32768 x 1024], mma.sync tf32
    gemm_mma_kernel<<<dim3(QKVO_COLS / 128, TOKENS / 128), 256, GEMM_SMEM>>>(
        x, W_qkvo, b_qkvo, qkvo_p, DIM, QKVO_COLS);

    // 2) kv_state / kmean / vmean partials + deterministic reduce
    kv_partial_kernel<<<dim3(32, NSPLIT), 1024>>>(qkvo_p, sin_, cos_);
    kv_reduce_kernel<<<32, 1024>>>();

    // 3) fused elementwise -> res*o
    combine_kernel<<<TOKENS / T3, 256>>>(qkvo_p, sin_, cos_, W_lepe, b_lepe, resO_p);

    // 4) out = resO @ W_proj^T + b_proj  [32768 x 256], mma.sync tf32
    gemm_mma_kernel<<<dim3(DIM / 128, TOKENS / 128), 256, GEMM_SMEM>>>(
        resO_p, W_proj, b_proj, out, INTERNAL, DIM);
}